// round 13
// baseline (speedup 1.0000x reference)
#include <cuda_runtime.h>
#include <cuda_fp16.h>
#include <math.h>

#define Ln 6
#define Bt 2
#define Qn 300
#define Dn 256
#define LP1 7

// ---------------- device scratch (no allocs allowed) ----------------
__device__ float g_Aproj[LP1*Bt*Qn*Dn];
__device__ float g_Bproj[LP1*Bt*Qn*Dn];
__device__ float g_gq[LP1*Bt*Qn];
__device__ float g_gk[LP1*Bt*Qn];
__device__ float g_Wc[2*LP1*Dn*Dn];    // composite weights fp32 (prep output)
__device__ float g_bc[2*LP1*Dn];
__device__ float g_wv[2*LP1*Dn];
__device__ float g_gb[2*LP1];
// W2 fp16 B-frags: idx = ((kt*32+gnt)*32+lane) -> uint2 {r0,r1}
__device__ uint2 g_W2frag[16*32*32];     // 128 KB
// Wc hi/lo fp16 B-frags: per (s,l) idx -> uint4 {hi_r0,hi_r1,lo_r0,lo_r1}
__device__ uint4 g_Wcfrag[2*LP1*16*32*32]; // 3.67 MB

// ---------------- small GEMM helper ----------------
template<int ROWS>
__device__ __forceinline__ void gemm_tile(const float* __restrict__ src,
                                          const float* __restrict__ W,
                                          const float* __restrict__ bias,
                                          float* __restrict__ out)
{
    __shared__ float ssrc[ROWS*Dn];
    int tid = threadIdx.x;
    for (int idx = tid; idx < ROWS*Dn/4; idx += 256)
        ((float4*)ssrc)[idx] = ((const float4*)src)[idx];
    __syncthreads();

    int e = tid;
    float acc[ROWS];
    #pragma unroll
    for (int r = 0; r < ROWS; r++) acc[r] = 0.f;

    for (int d = 0; d < Dn; d += 4) {
        float w0 = W[(d+0)*Dn + e];
        float w1 = W[(d+1)*Dn + e];
        float w2 = W[(d+2)*Dn + e];
        float w3 = W[(d+3)*Dn + e];
        #pragma unroll
        for (int r = 0; r < ROWS; r++) {
            float4 s4 = *(const float4*)&ssrc[r*Dn + d];
            acc[r] = fmaf(s4.x, w0, acc[r]);
            acc[r] = fmaf(s4.y, w1, acc[r]);
            acc[r] = fmaf(s4.z, w2, acc[r]);
            acc[r] = fmaf(s4.w, w3, acc[r]);
        }
    }
    float bv = bias ? bias[e] : 0.f;
    #pragma unroll
    for (int r = 0; r < ROWS; r++) out[r*Dn + e] = acc[r] + bv;
}

// ---- composite-weight prep (fp32 Wc, bc, wv, gb) ----
__global__ void __launch_bounds__(256)
kernel_prep(const float* __restrict__ Wq,  const float* __restrict__ bq,
            const float* __restrict__ Wk,  const float* __restrict__ bk,
            const float* __restrict__ Wsub,const float* __restrict__ bsub,
            const float* __restrict__ Wobj,const float* __restrict__ bobj,
            const float* __restrict__ Wg,  const float* __restrict__ bg,
            const float* __restrict__ W1)
{
    int tile = blockIdx.x;   // 0..7
    int l    = blockIdx.y;   // 0..6
    int s    = blockIdx.z;   // 0=a(Q), 1=b(K)
    const float* Wsrc = (l < Ln) ? ((s ? Wk : Wq) + (size_t)l*Dn*Dn) : (s ? Wobj : Wsub);
    const float* bsrc = (l < Ln) ? ((s ? bk : bq) + l*Dn) : (s ? bobj : bsub);
    const float* W1s  = W1 + (size_t)s*Dn*Dn;
    const float* wgv  = Wg + s*Dn;
    float* outW = g_Wc + (size_t)(s*LP1 + l)*Dn*Dn;

    gemm_tile<32>(Wsrc + (size_t)tile*32*Dn, W1s, nullptr, outW + (size_t)tile*32*Dn);

    int tid = threadIdx.x;
    if (tid < 32) {
        int row = tile*32 + tid;
        float sd = 0.f;
        for (int m = 0; m < Dn; m++) sd = fmaf(Wsrc[row*Dn + m], wgv[m], sd);
        g_wv[(s*LP1 + l)*Dn + row] = sd;
    }
    if (tile == 0) {
        int e = tid;
        float sd = 0.f;
        for (int d = 0; d < Dn; d++) sd = fmaf(bsrc[d], W1s[d*Dn + e], sd);
        g_bc[(s*LP1 + l)*Dn + e] = sd;
        if (tid == 0) {
            float sg = 0.f;
            for (int d = 0; d < Dn; d++) sg = fmaf(bsrc[d], wgv[d], sg);
            g_gb[s*LP1 + l] = sg + (s == 0 ? bg[0] : 0.f);
        }
    }
}

// ---- fragify Wc into fp16 hi/lo B-frags ----
__global__ void kernel_prepwc()
{
    int sl  = blockIdx.y;                     // 0..13
    int idx = blockIdx.x*256 + threadIdx.x;   // 0..16383
    int lane = idx & 31;
    int gnt  = (idx >> 5) & 31;
    int kt   = idx >> 10;
    int g = lane >> 2, tg = lane & 3;
    int n  = gnt*8 + g;
    int k0 = kt*16 + tg*2;
    const float* W = g_Wc + (size_t)sl*Dn*Dn;

    unsigned hr[2], lr[2];
    #pragma unroll
    for (int r = 0; r < 2; r++) {
        int ka = k0 + 8*r;
        float v0 = W[(size_t)ka*Dn + n];
        float v1 = W[(size_t)(ka+1)*Dn + n];
        __half h0 = __float2half(v0);
        __half h1 = __float2half(v1);
        __half l0 = __float2half(v0 - __half2float(h0));
        __half l1 = __float2half(v1 - __half2float(h1));
        __half2 hp; hp.x = h0; hp.y = h1;
        __half2 lp; lp.x = l0; lp.y = l1;
        hr[r] = *(unsigned*)&hp;
        lr[r] = *(unsigned*)&lp;
    }
    uint4 v; v.x = hr[0]; v.y = hr[1]; v.z = lr[0]; v.w = lr[1];
    g_Wcfrag[(size_t)sl*16384 + idx] = v;
}

// ---- W2 fp16 B-fragments ----
__global__ void kernel_prepw2(const float* __restrict__ W2)
{
    int idx = blockIdx.x*256 + threadIdx.x;   // 0..16383
    int lane = idx & 31;
    int gnt  = (idx >> 5) & 31;
    int kt   = idx >> 10;
    int g = lane >> 2, tg = lane & 3;
    int n  = gnt*8 + g;
    int k0 = kt*16 + tg*2;

    unsigned hr[2];
    #pragma unroll
    for (int r = 0; r < 2; r++) {
        int ka = k0 + 8*r;
        __half2 hp;
        hp.x = __float2half(W2[(size_t)ka*Dn + n]);
        hp.y = __float2half(W2[(size_t)(ka+1)*Dn + n]);
        hr[r] = *(unsigned*)&hp;
    }
    uint2 v; v.x = hr[0]; v.y = hr[1];
    g_W2frag[idx] = v;
}

__device__ __forceinline__ void mma16816(float* c, const unsigned* a,
                                         unsigned b0, unsigned b1)
{
    asm volatile(
        "mma.sync.aligned.m16n8k16.row.col.f32.f16.f16.f32 "
        "{%0,%1,%2,%3}, {%4,%5,%6,%7}, {%8,%9}, {%0,%1,%2,%3};"
        : "+f"(c[0]), "+f"(c[1]), "+f"(c[2]), "+f"(c[3])
        : "r"(a[0]), "r"(a[1]), "r"(a[2]), "r"(a[3]), "r"(b0), "r"(b1));
}

// ---- A/B projections via 3-term compensated HMMA + fused exact gate dots ----
#define HS2 264
#define PSM_HS   0                     // 32*256*4 = 32768
#define PSM_HI   32768                 // 32*264*2 = 16896
#define PSM_LO   (32768+16896)
#define PSM_TOTAL (32768+2*16896)      // 66560

__global__ void __launch_bounds__(256, 2)
kernel_projmma(const float* __restrict__ hs)
{
    extern __shared__ char psm[];
    float* hs32 = (float*)(psm + PSM_HS);
    __half* phi = (__half*)(psm + PSM_HI);
    __half* plo = (__half*)(psm + PSM_LO);

    int tid = threadIdx.x;
    int wid = tid >> 5, lane = tid & 31;
    int tile = blockIdx.x;   // 0..18
    int l    = blockIdx.y;   // 0..6
    int s    = blockIdx.z;
    int row0 = l*600 + tile*32;
    int rmax = l*600 + 599;
    int srcl = (l < Ln) ? l : (Ln - 1);

    for (int idx = tid; idx < 32*64; idx += 256) {
        int rr = idx >> 6, c4 = idx & 63;
        int grow = min(row0 + rr, rmax);
        int gg = grow - l*600;
        int b = gg / 300, q = gg % 300;
        const float4* src = (const float4*)(hs + ((size_t)((srcl*Bt + b)*Qn + q))*Dn);
        ((float4*)(hs32 + rr*Dn))[c4] = src[c4];
    }
    __syncthreads();

    {
        const float* wv = g_wv + (s*LP1 + l)*Dn;
        float gbv = g_gb[s*LP1 + l];
        for (int r = wid; r < 32; r += 8) {
            float sd = 0.f;
            #pragma unroll
            for (int u = 0; u < 8; u++)
                sd = fmaf(hs32[r*Dn + lane + 32*u], wv[lane + 32*u], sd);
            #pragma unroll
            for (int off = 16; off > 0; off >>= 1) sd += __shfl_xor_sync(0xffffffffu, sd, off);
            if (lane == 0) {
                int grow = min(row0 + r, rmax);
                float v = sd + gbv;
                if (s) g_gk[grow] = v;
                else   g_gq[grow] = v;
            }
        }
    }

    {
        int e = tid;
        #pragma unroll
        for (int r = 0; r < 32; r++) {
            float x = hs32[r*Dn + e];
            __half h = __float2half(x);
            __half lo = __float2half(x - __half2float(h));
            phi[r*HS2 + e] = h;
            plo[r*HS2 + e] = lo;
        }
    }
    __syncthreads();

    int g  = lane >> 2;
    int tg = lane & 3;
    int n0 = wid * 32;
    const uint4* base = g_Wcfrag + (size_t)(s*LP1 + l)*16384;

    float acc[2][4][4];
    #pragma unroll
    for (int mt = 0; mt < 2; mt++)
        #pragma unroll
        for (int nt = 0; nt < 4; nt++)
            #pragma unroll
            for (int c = 0; c < 4; c++) acc[mt][nt][c] = 0.f;

    #pragma unroll
    for (int kt = 0; kt < 16; kt++) {
        int k0 = kt*16 + tg*2;
        unsigned ahi[2][4], alo[2][4];
        #pragma unroll
        for (int mt = 0; mt < 2; mt++) {
            int r0 = mt*16;
            ahi[mt][0] = *(const unsigned*)&phi[(r0 + g    )*HS2 + k0];
            ahi[mt][1] = *(const unsigned*)&phi[(r0 + g + 8)*HS2 + k0];
            ahi[mt][2] = *(const unsigned*)&phi[(r0 + g    )*HS2 + k0 + 8];
            ahi[mt][3] = *(const unsigned*)&phi[(r0 + g + 8)*HS2 + k0 + 8];
            alo[mt][0] = *(const unsigned*)&plo[(r0 + g    )*HS2 + k0];
            alo[mt][1] = *(const unsigned*)&plo[(r0 + g + 8)*HS2 + k0];
            alo[mt][2] = *(const unsigned*)&plo[(r0 + g    )*HS2 + k0 + 8];
            alo[mt][3] = *(const unsigned*)&plo[(r0 + g + 8)*HS2 + k0 + 8];
        }
        #pragma unroll
        for (int nt = 0; nt < 4; nt++) {
            uint4 bf = base[((size_t)kt*32 + wid*4 + nt)*32 + lane];
            #pragma unroll
            for (int mt = 0; mt < 2; mt++) {
                mma16816(acc[mt][nt], ahi[mt], bf.x, bf.y);
                mma16816(acc[mt][nt], alo[mt], bf.x, bf.y);
                mma16816(acc[mt][nt], ahi[mt], bf.z, bf.w);
            }
        }
    }

    float* out = s ? g_Bproj : g_Aproj;
    const float* bc = g_bc + (s*LP1 + l)*Dn;
    #pragma unroll
    for (int mt = 0; mt < 2; mt++) {
        int w0 = min(row0 + mt*16 + g,     rmax);
        int w1 = min(row0 + mt*16 + g + 8, rmax);
        #pragma unroll
        for (int nt = 0; nt < 4; nt++) {
            int c = n0 + nt*8 + tg*2;
            float bc0 = bc[c], bc1 = bc[c+1];
            out[(size_t)w0*Dn + c]     = acc[mt][nt][0] + bc0;
            out[(size_t)w0*Dn + c + 1] = acc[mt][nt][1] + bc1;
            out[(size_t)w1*Dn + c]     = acc[mt][nt][2] + bc0;
            out[(size_t)w1*Dn + c + 1] = acc[mt][nt][3] + bc1;
        }
    }
}

// ---------------- main fused kernel (3 blocks/SM, reduced live regs) ----------------
#define HS 264
#define SM_GATES 0
#define SM_B2    3584
#define SM_W3    4608
#define SM_HHI   5632
#define SMEM_TOTAL (5632 + 67584)   // 73216

__global__ void __launch_bounds__(256, 3)
kernel_main(const float* __restrict__ b1, const float* __restrict__ b2g,
            const float* __restrict__ W3, const float* __restrict__ b3,
            float* __restrict__ out)
{
    extern __shared__ char smem[];
    float* gates = (float*)(smem + SM_GATES);
    float* b2s   = (float*)(smem + SM_B2);
    float* w3s   = (float*)(smem + SM_W3);
    __half* hhi = (__half*)(smem + SM_HHI);

    int tid = threadIdx.x;
    int wid = tid >> 5, lane = tid & 31;
    int j0 = blockIdx.x*4;
    int i0 = blockIdx.y*32;
    int b  = blockIdx.z;

    b2s[tid] = b2g[tid];
    w3s[tid] = W3[tid];
    for (int t = tid; t < LP1*128; t += 256) {
        int l = t >> 7, p = t & 127;
        int i = min(i0 + (p >> 2), Qn - 1);
        int j = min(j0 + (p & 3),  Qn - 1);
        float z = g_gq[(l*Bt + b)*Qn + i] + g_gk[(l*Bt + b)*Qn + j];
        gates[t] = 1.f / (1.f + expf(-z));
    }
    __syncthreads();

    // ---- phase 1: 8 sub-chunks of 16 pairs (4i x 4j) — low live-register count ----
    {
        int e = tid;
        float b1e = b1[e];
        for (int g8 = 0; g8 < 8; g8++) {
            float acc[16];
            #pragma unroll
            for (int p = 0; p < 16; p++) acc[p] = 0.f;
            #pragma unroll
            for (int l = 0; l < LP1; l++) {
                const float* Ab = g_Aproj + (size_t)(l*Bt + b)*Qn*Dn;
                const float* Bb = g_Bproj + (size_t)(l*Bt + b)*Qn*Dn;
                float av[4], bvv[4];
                #pragma unroll
                for (int ii = 0; ii < 4; ii++)
                    av[ii] = Ab[(size_t)min(i0 + g8*4 + ii, Qn - 1)*Dn + e];
                #pragma unroll
                for (int jj = 0; jj < 4; jj++)
                    bvv[jj] = Bb[(size_t)min(j0 + jj, Qn - 1)*Dn + e];
                const float* gl = &gates[l*128 + g8*16];
                #pragma unroll
                for (int ii = 0; ii < 4; ii++)
                    #pragma unroll
                    for (int jj = 0; jj < 4; jj++) {
                        int p = ii*4 + jj;
                        acc[p] = fmaf(gl[p], av[ii] + bvv[jj], acc[p]);
                    }
            }
            #pragma unroll
            for (int p = 0; p < 16; p++) {
                int row = g8*16 + p;
                hhi[row*HS + e] = __float2half(fmaxf(acc[p] + b1e, 0.f));
            }
        }
    }
    __syncthreads();

    // ---- phase 2: fp16 HMMA GEMM, 4 chunks of 8 n-tiles ----
    int g  = lane >> 2;
    int tg = lane & 3;
    int rb = wid * 16;
    float s_g = 0.f, s_g8 = 0.f;

    #pragma unroll
    for (int nc = 0; nc < 4; nc++) {
        float acc[8][4];
        #pragma unroll
        for (int nt = 0; nt < 8; nt++)
            #pragma unroll
            for (int c = 0; c < 4; c++) acc[nt][c] = 0.f;

        #pragma unroll
        for (int kt = 0; kt < 16; kt++) {
            int k0 = kt*16 + tg*2;
            unsigned ahi[4];
            ahi[0] = *(const unsigned*)&hhi[(rb + g    )*HS + k0];
            ahi[1] = *(const unsigned*)&hhi[(rb + g + 8)*HS + k0];
            ahi[2] = *(const unsigned*)&hhi[(rb + g    )*HS + k0 + 8];
            ahi[3] = *(const unsigned*)&hhi[(rb + g + 8)*HS + k0 + 8];

            const uint2* fr = &g_W2frag[((size_t)kt*32 + nc*8)*32 + lane];
            #pragma unroll
            for (int nt = 0; nt < 8; nt++) {
                uint2 bf = fr[nt*32];
                mma16816(acc[nt], ahi, bf.x, bf.y);
            }
        }

        #pragma unroll
        for (int nt = 0; nt < 8; nt++) {
            int n0 = (nc*8 + nt)*8 + tg*2;
            float w0 = w3s[n0], w1 = w3s[n0+1];
            float c0 = b2s[n0], c1 = b2s[n0+1];
            s_g  = fmaf(fmaxf(acc[nt][0] + c0, 0.f), w0, s_g);
            s_g  = fmaf(fmaxf(acc[nt][1] + c1, 0.f), w1, s_g);
            s_g8 = fmaf(fmaxf(acc[nt][2] + c0, 0.f), w0, s_g8);
            s_g8 = fmaf(fmaxf(acc[nt][3] + c1, 0.f), w1, s_g8);
        }
    }

    #pragma unroll
    for (int off = 1; off <= 2; off <<= 1) {
        s_g  += __shfl_xor_sync(0xffffffffu, s_g,  off);
        s_g8 += __shfl_xor_sync(0xffffffffu, s_g8, off);
    }
    if (tg == 0) {
        float b3v = b3[0];
        int rows[2] = { rb + g, rb + 8 + g };
        float vals[2] = { s_g + b3v, s_g8 + b3v };
        #pragma unroll
        for (int u = 0; u < 2; u++) {
            int p = rows[u];
            int i = i0 + (p >> 2), j = j0 + (p & 3);
            if (i < Qn && j < Qn) {
                float pred = vals[u];
                #pragma unroll
                for (int lay = 0; lay < Ln; lay++)
                    out[((size_t)(lay*Bt + b)*Qn + i)*Qn + j] = pred;
            }
        }
    }
}

extern "C" void kernel_launch(void* const* d_in, const int* in_sizes, int n_in,
                              void* d_out, int out_size)
{
    const float* hs   = (const float*)d_in[0];
    const float* Wq   = (const float*)d_in[1];
    const float* bq   = (const float*)d_in[2];
    const float* Wk   = (const float*)d_in[3];
    const float* bk   = (const float*)d_in[4];
    const float* Wsub = (const float*)d_in[5];
    const float* bsub = (const float*)d_in[6];
    const float* Wobj = (const float*)d_in[7];
    const float* bobj = (const float*)d_in[8];
    const float* Wg   = (const float*)d_in[9];
    const float* bg   = (const float*)d_in[10];
    const float* W1   = (const float*)d_in[11];
    const float* b1   = (const float*)d_in[12];
    const float* W2   = (const float*)d_in[13];
    const float* b2   = (const float*)d_in[14];
    const float* W3   = (const float*)d_in[15];
    const float* b3   = (const float*)d_in[16];
    float* out = (float*)d_out;

    cudaFuncSetAttribute(kernel_main,    cudaFuncAttributeMaxDynamicSharedMemorySize, SMEM_TOTAL);
    cudaFuncSetAttribute(kernel_projmma, cudaFuncAttributeMaxDynamicSharedMemorySize, PSM_TOTAL);

    kernel_prep   <<<dim3(8, 7, 2),   256>>>(Wq, bq, Wk, bk, Wsub, bsub, Wobj, bobj, Wg, bg, W1);
    kernel_prepwc <<<dim3(64, 14),    256>>>();
    kernel_prepw2 <<<64,              256>>>(W2);
    kernel_projmma<<<dim3(19, 7, 2),  256, PSM_TOTAL>>>(hs);
    kernel_main   <<<dim3(75, 10, 2), 256, SMEM_TOTAL>>>(b1, b2, W3, b3, out);
}

// round 14
// speedup vs baseline: 2.3242x; 2.3242x over previous
#include <cuda_runtime.h>
#include <cuda_fp16.h>
#include <math.h>

#define Ln 6
#define Bt 2
#define Qn 300
#define Dn 256
#define LP1 7

// ---------------- device scratch (no allocs allowed) ----------------
__device__ float g_Aproj[LP1*Bt*Qn*Dn];
__device__ float g_Bproj[LP1*Bt*Qn*Dn];
__device__ float g_gq[LP1*Bt*Qn];
__device__ float g_gk[LP1*Bt*Qn];
__device__ float g_Wc[2*LP1*Dn*Dn];    // composite weights fp32 (prep output)
__device__ float g_bc[2*LP1*Dn];
__device__ float g_wv[2*LP1*Dn];
__device__ float g_gb[2*LP1];
// W2 fp16 B-frags, PAIRED layout (R8-validated):
// entry[(kt*16+np)*32+lane] = uint4 {nt=2np: r0,r1, nt=2np+1: r0,r1}
__device__ uint4 g_W2frag4[16*16*32];      // 128 KB
// Wc hi/lo fp16 B-frags: per (s,l) idx -> uint4 {hi_r0,hi_r1,lo_r0,lo_r1}
__device__ uint4 g_Wcfrag[2*LP1*16*32*32]; // 3.67 MB

__device__ __forceinline__ unsigned smem_u32(const void* p) {
    unsigned a;
    asm("{ .reg .u64 t; cvta.to.shared.u64 t, %1; cvt.u32.u64 %0, t; }" : "=r"(a) : "l"(p));
    return a;
}

// ---------------- small GEMM helper ----------------
template<int ROWS>
__device__ __forceinline__ void gemm_tile(const float* __restrict__ src,
                                          const float* __restrict__ W,
                                          const float* __restrict__ bias,
                                          float* __restrict__ out)
{
    __shared__ float ssrc[ROWS*Dn];
    int tid = threadIdx.x;
    for (int idx = tid; idx < ROWS*Dn/4; idx += 256)
        ((float4*)ssrc)[idx] = ((const float4*)src)[idx];
    __syncthreads();

    int e = tid;
    float acc[ROWS];
    #pragma unroll
    for (int r = 0; r < ROWS; r++) acc[r] = 0.f;

    for (int d = 0; d < Dn; d += 4) {
        float w0 = W[(d+0)*Dn + e];
        float w1 = W[(d+1)*Dn + e];
        float w2 = W[(d+2)*Dn + e];
        float w3 = W[(d+3)*Dn + e];
        #pragma unroll
        for (int r = 0; r < ROWS; r++) {
            float4 s4 = *(const float4*)&ssrc[r*Dn + d];
            acc[r] = fmaf(s4.x, w0, acc[r]);
            acc[r] = fmaf(s4.y, w1, acc[r]);
            acc[r] = fmaf(s4.z, w2, acc[r]);
            acc[r] = fmaf(s4.w, w3, acc[r]);
        }
    }
    float bv = bias ? bias[e] : 0.f;
    #pragma unroll
    for (int r = 0; r < ROWS; r++) out[r*Dn + e] = acc[r] + bv;
}

// ---- composite-weight prep (fp32 Wc, bc, wv, gb) + fused W2 fragify ----
__global__ void __launch_bounds__(256)
kernel_prep(const float* __restrict__ Wq,  const float* __restrict__ bq,
            const float* __restrict__ Wk,  const float* __restrict__ bk,
            const float* __restrict__ Wsub,const float* __restrict__ bsub,
            const float* __restrict__ Wobj,const float* __restrict__ bobj,
            const float* __restrict__ Wg,  const float* __restrict__ bg,
            const float* __restrict__ W1,  const float* __restrict__ W2)
{
    int tile = blockIdx.x;   // 0..7
    int l    = blockIdx.y;   // 0..6
    int s    = blockIdx.z;   // 0=a(Q), 1=b(K)
    const float* Wsrc = (l < Ln) ? ((s ? Wk : Wq) + (size_t)l*Dn*Dn) : (s ? Wobj : Wsub);
    const float* bsrc = (l < Ln) ? ((s ? bk : bq) + l*Dn) : (s ? bobj : bsub);
    const float* W1s  = W1 + (size_t)s*Dn*Dn;
    const float* wgv  = Wg + s*Dn;
    float* outW = g_Wc + (size_t)(s*LP1 + l)*Dn*Dn;

    gemm_tile<32>(Wsrc + (size_t)tile*32*Dn, W1s, nullptr, outW + (size_t)tile*32*Dn);

    int tid = threadIdx.x;
    if (tid < 32) {
        int row = tile*32 + tid;
        float sd = 0.f;
        for (int m = 0; m < Dn; m++) sd = fmaf(Wsrc[row*Dn + m], wgv[m], sd);
        g_wv[(s*LP1 + l)*Dn + row] = sd;
    }
    if (tile == 0) {
        int e = tid;
        float sd = 0.f;
        for (int d = 0; d < Dn; d++) sd = fmaf(bsrc[d], W1s[d*Dn + e], sd);
        g_bc[(s*LP1 + l)*Dn + e] = sd;
        if (tid == 0) {
            float sg = 0.f;
            for (int d = 0; d < Dn; d++) sg = fmaf(bsrc[d], wgv[d], sg);
            g_gb[s*LP1 + l] = sg + (s == 0 ? bg[0] : 0.f);
        }
    }

    // fused W2 fragify (first 32 blocks in linear order): paired uint4 layout
    int blin = blockIdx.x + 8*(blockIdx.y + 7*blockIdx.z);
    if (blin < 32) {
        int idx = blin*256 + tid;   // 0..8191
        int lane = idx & 31;
        int np   = (idx >> 5) & 15;
        int kt   = idx >> 9;
        int g = lane >> 2, tg = lane & 3;
        int k0 = kt*16 + tg*2;

        unsigned hr[2][2];
        #pragma unroll
        for (int h = 0; h < 2; h++) {
            int n = (2*np + h)*8 + g;
            #pragma unroll
            for (int r = 0; r < 2; r++) {
                int ka = k0 + 8*r;
                __half2 hp;
                hp.x = __float2half(W2[(size_t)ka*Dn + n]);
                hp.y = __float2half(W2[(size_t)(ka+1)*Dn + n]);
                hr[h][r] = *(unsigned*)&hp;
            }
        }
        uint4 v; v.x = hr[0][0]; v.y = hr[0][1]; v.z = hr[1][0]; v.w = hr[1][1];
        g_W2frag4[idx] = v;
    }
}

// ---- fragify Wc into fp16 hi/lo B-frags ----
__global__ void kernel_prepwc()
{
    int sl  = blockIdx.y;                     // 0..13
    int idx = blockIdx.x*256 + threadIdx.x;   // 0..16383
    int lane = idx & 31;
    int gnt  = (idx >> 5) & 31;
    int kt   = idx >> 10;
    int g = lane >> 2, tg = lane & 3;
    int n  = gnt*8 + g;
    int k0 = kt*16 + tg*2;
    const float* W = g_Wc + (size_t)sl*Dn*Dn;

    unsigned hr[2], lr[2];
    #pragma unroll
    for (int r = 0; r < 2; r++) {
        int ka = k0 + 8*r;
        float v0 = W[(size_t)ka*Dn + n];
        float v1 = W[(size_t)(ka+1)*Dn + n];
        __half h0 = __float2half(v0);
        __half h1 = __float2half(v1);
        __half l0 = __float2half(v0 - __half2float(h0));
        __half l1 = __float2half(v1 - __half2float(h1));
        __half2 hp; hp.x = h0; hp.y = h1;
        __half2 lp; lp.x = l0; lp.y = l1;
        hr[r] = *(unsigned*)&hp;
        lr[r] = *(unsigned*)&lp;
    }
    uint4 v; v.x = hr[0]; v.y = hr[1]; v.z = lr[0]; v.w = lr[1];
    g_Wcfrag[(size_t)sl*16384 + idx] = v;
}

__device__ __forceinline__ void mma16816(float* c, const unsigned* a,
                                         unsigned b0, unsigned b1)
{
    asm volatile(
        "mma.sync.aligned.m16n8k16.row.col.f32.f16.f16.f32 "
        "{%0,%1,%2,%3}, {%4,%5,%6,%7}, {%8,%9}, {%0,%1,%2,%3};"
        : "+f"(c[0]), "+f"(c[1]), "+f"(c[2]), "+f"(c[3])
        : "r"(a[0]), "r"(a[1]), "r"(a[2]), "r"(a[3]), "r"(b0), "r"(b1));
}

// ---- A/B projections via 3-term compensated HMMA + fused exact gate dots ----
#define HS2 264
#define PSM_HS   0                     // 32*256*4 = 32768
#define PSM_HI   32768                 // 32*264*2 = 16896
#define PSM_LO   (32768+16896)
#define PSM_TOTAL (32768+2*16896)      // 66560

__global__ void __launch_bounds__(256, 2)
kernel_projmma(const float* __restrict__ hs)
{
    extern __shared__ char psm[];
    float* hs32 = (float*)(psm + PSM_HS);
    __half* phi = (__half*)(psm + PSM_HI);
    __half* plo = (__half*)(psm + PSM_LO);

    int tid = threadIdx.x;
    int wid = tid >> 5, lane = tid & 31;
    int tile = blockIdx.x;   // 0..18
    int l    = blockIdx.y;   // 0..6
    int s    = blockIdx.z;
    int row0 = l*600 + tile*32;
    int rmax = l*600 + 599;
    int srcl = (l < Ln) ? l : (Ln - 1);

    for (int idx = tid; idx < 32*64; idx += 256) {
        int rr = idx >> 6, c4 = idx & 63;
        int grow = min(row0 + rr, rmax);
        int gg = grow - l*600;
        int b = gg / 300, q = gg % 300;
        const float4* src = (const float4*)(hs + ((size_t)((srcl*Bt + b)*Qn + q))*Dn);
        ((float4*)(hs32 + rr*Dn))[c4] = src[c4];
    }
    __syncthreads();

    {
        const float* wv = g_wv + (s*LP1 + l)*Dn;
        float gbv = g_gb[s*LP1 + l];
        for (int r = wid; r < 32; r += 8) {
            float sd = 0.f;
            #pragma unroll
            for (int u = 0; u < 8; u++)
                sd = fmaf(hs32[r*Dn + lane + 32*u], wv[lane + 32*u], sd);
            #pragma unroll
            for (int off = 16; off > 0; off >>= 1) sd += __shfl_xor_sync(0xffffffffu, sd, off);
            if (lane == 0) {
                int grow = min(row0 + r, rmax);
                float v = sd + gbv;
                if (s) g_gk[grow] = v;
                else   g_gq[grow] = v;
            }
        }
    }

    {
        int e = tid;
        #pragma unroll
        for (int r = 0; r < 32; r++) {
            float x = hs32[r*Dn + e];
            __half h = __float2half(x);
            __half lo = __float2half(x - __half2float(h));
            phi[r*HS2 + e] = h;
            plo[r*HS2 + e] = lo;
        }
    }
    __syncthreads();

    int g  = lane >> 2;
    int tg = lane & 3;
    int n0 = wid * 32;
    const uint4* base = g_Wcfrag + (size_t)(s*LP1 + l)*16384;

    float acc[2][4][4];
    #pragma unroll
    for (int mt = 0; mt < 2; mt++)
        #pragma unroll
        for (int nt = 0; nt < 4; nt++)
            #pragma unroll
            for (int c = 0; c < 4; c++) acc[mt][nt][c] = 0.f;

    #pragma unroll
    for (int kt = 0; kt < 16; kt++) {
        int k0 = kt*16 + tg*2;
        unsigned ahi[2][4], alo[2][4];
        #pragma unroll
        for (int mt = 0; mt < 2; mt++) {
            int r0 = mt*16;
            ahi[mt][0] = *(const unsigned*)&phi[(r0 + g    )*HS2 + k0];
            ahi[mt][1] = *(const unsigned*)&phi[(r0 + g + 8)*HS2 + k0];
            ahi[mt][2] = *(const unsigned*)&phi[(r0 + g    )*HS2 + k0 + 8];
            ahi[mt][3] = *(const unsigned*)&phi[(r0 + g + 8)*HS2 + k0 + 8];
            alo[mt][0] = *(const unsigned*)&plo[(r0 + g    )*HS2 + k0];
            alo[mt][1] = *(const unsigned*)&plo[(r0 + g + 8)*HS2 + k0];
            alo[mt][2] = *(const unsigned*)&plo[(r0 + g    )*HS2 + k0 + 8];
            alo[mt][3] = *(const unsigned*)&plo[(r0 + g + 8)*HS2 + k0 + 8];
        }
        #pragma unroll
        for (int nt = 0; nt < 4; nt++) {
            uint4 bf = base[((size_t)kt*32 + wid*4 + nt)*32 + lane];
            #pragma unroll
            for (int mt = 0; mt < 2; mt++) {
                mma16816(acc[mt][nt], ahi[mt], bf.x, bf.y);
                mma16816(acc[mt][nt], alo[mt], bf.x, bf.y);
                mma16816(acc[mt][nt], ahi[mt], bf.z, bf.w);
            }
        }
    }

    float* out = s ? g_Bproj : g_Aproj;
    const float* bc = g_bc + (s*LP1 + l)*Dn;
    #pragma unroll
    for (int mt = 0; mt < 2; mt++) {
        int w0 = min(row0 + mt*16 + g,     rmax);
        int w1 = min(row0 + mt*16 + g + 8, rmax);
        #pragma unroll
        for (int nt = 0; nt < 4; nt++) {
            int c = n0 + nt*8 + tg*2;
            float bc0 = bc[c], bc1 = bc[c+1];
            out[(size_t)w0*Dn + c]     = acc[mt][nt][0] + bc0;
            out[(size_t)w0*Dn + c + 1] = acc[mt][nt][1] + bc1;
            out[(size_t)w1*Dn + c]     = acc[mt][nt][2] + bc0;
            out[(size_t)w1*Dn + c + 1] = acc[mt][nt][3] + bc1;
        }
    }
}

// ---------------- main fused kernel (R12 structure + issue-slot cuts) ----------------
#define HS 264
#define SM_GATES 0
#define SM_B2    3584
#define SM_W3    4608
#define SM_HHI   5632
#define SMEM_TOTAL (5632 + 67584)   // 73216

__global__ void __launch_bounds__(256, 2)
kernel_main(const float* __restrict__ b1, const float* __restrict__ b2g,
            const float* __restrict__ W3, const float* __restrict__ b3,
            float* __restrict__ out)
{
    extern __shared__ char smem[];
    float* gates = (float*)(smem + SM_GATES);
    float* b2s   = (float*)(smem + SM_B2);
    float* w3s   = (float*)(smem + SM_W3);
    __half* hhi = (__half*)(smem + SM_HHI);

    int tid = threadIdx.x;
    int wid = tid >> 5, lane = tid & 31;
    int j0 = blockIdx.x*4;
    int i0 = blockIdx.y*32;
    int b  = blockIdx.z;

    b2s[tid] = b2g[tid];
    w3s[tid] = W3[tid];
    for (int t = tid; t < LP1*128; t += 256) {
        int l = t >> 7, p = t & 127;
        int i = min(i0 + (p >> 2), Qn - 1);
        int j = min(j0 + (p & 3),  Qn - 1);
        float z = g_gq[(l*Bt + b)*Qn + i] + g_gk[(l*Bt + b)*Qn + j];
        gates[t] = 1.f / (1.f + expf(-z));
    }
    __syncthreads();

    // ---- phase 1: h1 = relu(sum_l gate*(A_i + B_j) + b1) -> fp16 smem (R12 proven) ----
    {
        int e = tid;
        float b1e = b1[e];
        for (int g4 = 0; g4 < 4; g4++) {
            float acc[32];
            #pragma unroll
            for (int p = 0; p < 32; p++) acc[p] = 0.f;
            #pragma unroll
            for (int l = 0; l < LP1; l++) {
                const float* Ab = g_Aproj + (size_t)(l*Bt + b)*Qn*Dn;
                const float* Bb = g_Bproj + (size_t)(l*Bt + b)*Qn*Dn;
                float av[8], bvv[4];
                #pragma unroll
                for (int ii = 0; ii < 8; ii++)
                    av[ii] = Ab[(size_t)min(i0 + g4*8 + ii, Qn - 1)*Dn + e];
                #pragma unroll
                for (int jj = 0; jj < 4; jj++)
                    bvv[jj] = Bb[(size_t)min(j0 + jj, Qn - 1)*Dn + e];
                const float* gl = &gates[l*128 + g4*32];
                #pragma unroll
                for (int ii = 0; ii < 8; ii++)
                    #pragma unroll
                    for (int jj = 0; jj < 4; jj++) {
                        int p = ii*4 + jj;
                        acc[p] = fmaf(gl[p], av[ii] + bvv[jj], acc[p]);
                    }
            }
            #pragma unroll
            for (int p = 0; p < 32; p++) {
                int row = g4*32 + p;
                hhi[row*HS + e] = __float2half(fmaxf(acc[p] + b1e, 0.f));
            }
        }
    }
    __syncthreads();

    // ---- phase 2: fp16 HMMA, 4 chunks of 8 n-tiles; ldmatrix A + paired uint4 B ----
    int g  = lane >> 2;
    int tg = lane & 3;
    int rb = wid * 16;
    float s_g = 0.f, s_g8 = 0.f;

    // ldmatrix lane address (R7-validated layout): tile tt = lane>>3, row r7 = lane&7
    unsigned abase;
    {
        int tt = lane >> 3, r7 = lane & 7;
        abase = smem_u32(hhi) + (unsigned)((rb + (tt & 1)*8 + r7)*HS + (tt >> 1)*8)*2u;
    }

    #pragma unroll
    for (int nc = 0; nc < 4; nc++) {
        float acc[8][4];
        #pragma unroll
        for (int nt = 0; nt < 8; nt++)
            #pragma unroll
            for (int c = 0; c < 4; c++) acc[nt][c] = 0.f;

        #pragma unroll
        for (int kt = 0; kt < 16; kt++) {
            unsigned af[4];
            asm volatile("ldmatrix.sync.aligned.m8n8.x4.shared.b16 {%0,%1,%2,%3}, [%4];"
                         : "=r"(af[0]), "=r"(af[1]), "=r"(af[2]), "=r"(af[3])
                         : "r"(abase + (unsigned)kt*32u));

            const uint4* fr = &g_W2frag4[((kt*16 + nc*4) << 5) + lane];
            #pragma unroll
            for (int np = 0; np < 4; np++) {
                uint4 bf = fr[np*32];
                mma16816(acc[2*np],     af, bf.x, bf.y);
                mma16816(acc[2*np + 1], af, bf.z, bf.w);
            }
        }

        #pragma unroll
        for (int nt = 0; nt < 8; nt++) {
            int n0 = (nc*8 + nt)*8 + tg*2;
            float w0 = w3s[n0], w1 = w3s[n0+1];
            float c0 = b2s[n0], c1 = b2s[n0+1];
            s_g  = fmaf(fmaxf(acc[nt][0] + c0, 0.f), w0, s_g);
            s_g  = fmaf(fmaxf(acc[nt][1] + c1, 0.f), w1, s_g);
            s_g8 = fmaf(fmaxf(acc[nt][2] + c0, 0.f), w0, s_g8);
            s_g8 = fmaf(fmaxf(acc[nt][3] + c1, 0.f), w1, s_g8);
        }
    }

    #pragma unroll
    for (int off = 1; off <= 2; off <<= 1) {
        s_g  += __shfl_xor_sync(0xffffffffu, s_g,  off);
        s_g8 += __shfl_xor_sync(0xffffffffu, s_g8, off);
    }
    if (tg == 0) {
        float b3v = b3[0];
        int rows[2] = { rb + g, rb + 8 + g };
        float vals[2] = { s_g + b3v, s_g8 + b3v };
        #pragma unroll
        for (int u = 0; u < 2; u++) {
            int p = rows[u];
            int i = i0 + (p >> 2), j = j0 + (p & 3);
            if (i < Qn && j < Qn) {
                float pred = vals[u];
                #pragma unroll
                for (int lay = 0; lay < Ln; lay++)
                    out[((size_t)(lay*Bt + b)*Qn + i)*Qn + j] = pred;
            }
        }
    }
}

extern "C" void kernel_launch(void* const* d_in, const int* in_sizes, int n_in,
                              void* d_out, int out_size)
{
    const float* hs   = (const float*)d_in[0];
    const float* Wq   = (const float*)d_in[1];
    const float* bq   = (const float*)d_in[2];
    const float* Wk   = (const float*)d_in[3];
    const float* bk   = (const float*)d_in[4];
    const float* Wsub = (const float*)d_in[5];
    const float* bsub = (const float*)d_in[6];
    const float* Wobj = (const float*)d_in[7];
    const float* bobj = (const float*)d_in[8];
    const float* Wg   = (const float*)d_in[9];
    const float* bg   = (const float*)d_in[10];
    const float* W1   = (const float*)d_in[11];
    const float* b1   = (const float*)d_in[12];
    const float* W2   = (const float*)d_in[13];
    const float* b2   = (const float*)d_in[14];
    const float* W3   = (const float*)d_in[15];
    const float* b3   = (const float*)d_in[16];
    float* out = (float*)d_out;

    cudaFuncSetAttribute(kernel_main,    cudaFuncAttributeMaxDynamicSharedMemorySize, SMEM_TOTAL);
    cudaFuncSetAttribute(kernel_projmma, cudaFuncAttributeMaxDynamicSharedMemorySize, PSM_TOTAL);

    kernel_prep   <<<dim3(8, 7, 2),   256>>>(Wq, bq, Wk, bk, Wsub, bsub, Wobj, bobj, Wg, bg, W1, W2);
    kernel_prepwc <<<dim3(64, 14),    256>>>();
    kernel_projmma<<<dim3(19, 7, 2),  256, PSM_TOTAL>>>(hs);
    kernel_main   <<<dim3(75, 10, 2), 256, SMEM_TOTAL>>>(b1, b2, W3, b3, out);
}